// round 15
// baseline (speedup 1.0000x reference)
#include <cuda_runtime.h>
#include <cuda_fp16.h>
#include <cstdint>

using f16 = __half;
#define DEVINLINE __device__ __forceinline__

static constexpr int CH    = 512;
static constexpr int HWDIM = 1024;
static constexpr int BATCH = 32;
static constexpr int NALL  = BATCH * HWDIM;   // 32768

static constexpr float WO_SCALE   = 4096.f;
static constexpr float WO_UNSCALE = 1.f / 4096.f;
static constexpr float SCALE_S    = 0.04419417382415922f;  // 512^-0.5

// ---------------- scratch ----------------------------------------------------
// g_W slots: 0=WkT, 1=WqT, 2=Wo_s(row-major, x4096), 3=WvT
__device__ f16   g_W [4 * CH * CH];
__device__ f16   g_M [2 * CH * CH];                  // 0=MsT, 1=Mo
__device__ f16   g_XT[(size_t)NALL * CH];            // [token][c]
__device__ f16   g_T [(size_t)NALL * CH];            // [token][c']  = X*Ms
__device__ f16   g_U [(size_t)CH * NALL];            // [r][token]   = Mo*X^T
__device__ f16   g_P [(size_t)BATCH * HWDIM * HWDIM];
__device__ float g_A2[CH], g_WOBV[CH];

// ---------------- helpers ------------------------------------------------------
DEVINLINE void ldsm4(uint32_t& r0, uint32_t& r1, uint32_t& r2, uint32_t& r3,
                     const f16* p) {
    uint32_t addr = (uint32_t)__cvta_generic_to_shared(p);
    asm volatile("ldmatrix.sync.aligned.m8n8.x4.shared.b16 {%0,%1,%2,%3}, [%4];"
                 : "=r"(r0), "=r"(r1), "=r"(r2), "=r"(r3) : "r"(addr));
}

DEVINLINE void mma_f16(uint32_t c[2], const uint32_t a[4], const uint32_t b[2]) {
    asm volatile("mma.sync.aligned.m16n8k16.row.col.f16.f16.f16.f16 "
                 "{%0,%1},{%2,%3,%4,%5},{%6,%7},{%0,%1};"
                 : "+r"(c[0]), "+r"(c[1])
                 : "r"(a[0]), "r"(a[1]), "r"(a[2]), "r"(a[3]),
                   "r"(b[0]), "r"(b[1]));
}

DEVINLINE void cp16(f16* dst, const f16* src) {
    uint32_t d = (uint32_t)__cvta_generic_to_shared(dst);
    asm volatile("cp.async.cg.shared.global [%0], [%1], 16;" :: "r"(d), "l"(src));
}
DEVINLINE void cp_commit() { asm volatile("cp.async.commit_group;"); }
template<int N> DEVINLINE void cp_wait() {
    asm volatile("cp.async.wait_group %0;" :: "n"(N));
}

DEVINLINE float hsum2(uint32_t h) {
    float2 f = __half22float2(*reinterpret_cast<const __half2*>(&h));
    return f.x + f.y;
}

// ---------------- prep kernels ---------------------------------------------------
// z=0: WkT<-Wk  z=1: WqT<-Wq  z=2: Wo_s copy(x4096)  z=3: WvT<-Wv
__global__ void convert_w_kernel(const float* __restrict__ wq, const float* __restrict__ wk,
                                 const float* __restrict__ wv, const float* __restrict__ wo,
                                 f16* __restrict__ W) {
    __shared__ float t[32][33];
    const int z = blockIdx.z;
    const float* src = (z == 0) ? wk : (z == 1) ? wq : (z == 2) ? wo : wv;
    f16* dst = W + (size_t)z * CH * CH;
    const int r0 = blockIdx.y * 32, c0 = blockIdx.x * 32;
    const int tx = threadIdx.x, ty = threadIdx.y;
    if (z == 2) {
        dst[(size_t)(r0 + ty) * CH + c0 + tx] =
            __float2half(src[(size_t)(r0 + ty) * CH + c0 + tx] * WO_SCALE);
    } else {
        t[ty][tx] = src[(size_t)(r0 + ty) * CH + c0 + tx];
        __syncthreads();
        dst[(size_t)(c0 + ty) * CH + r0 + tx] = __float2half(t[tx][ty]);
    }
}

// x [B][C][HW] fp32 -> XT [B*HW][C] f16.  64x64 tiles, float4 loads,
// pad-65 smem (conflict-free column reads), uint4 f16 stores.
__global__ void __launch_bounds__(256)
xt_kernel(const float* __restrict__ x, f16* __restrict__ XT) {
    __shared__ float tile[64][65];
    const int b  = blockIdx.z;
    const int s0 = blockIdx.x * 64;
    const int c0 = blockIdx.y * 64;
    const int t  = threadIdx.x;
    const int r  = t >> 4;             // 0..15
    const int q4 = (t & 15) * 4;       // float col (0,4,...,60)
    #pragma unroll
    for (int i = 0; i < 4; ++i) {
        const int row = r + i * 16;
        const float4 v = *(const float4*)(x + ((size_t)b * CH + c0 + row) * HWDIM + s0 + q4);
        tile[row][q4]     = v.x;
        tile[row][q4 + 1] = v.y;
        tile[row][q4 + 2] = v.z;
        tile[row][q4 + 3] = v.w;
    }
    __syncthreads();
    #pragma unroll
    for (int i = 0; i < 2; ++i) {
        const int q  = t + i * 256;
        const int j  = q >> 3;          // token within tile (0..63)
        const int cc = (q & 7) * 8;     // channel chunk
        f16 buf[8];
        #pragma unroll
        for (int e = 0; e < 8; ++e)
            buf[e] = __float2half(tile[cc + e][j]);
        *(uint4*)(XT + ((size_t)b * HWDIM + s0 + j) * CH + c0 + cc) = *(uint4*)buf;
    }
}

// a2 = Wk^T bq, wobv = WO_SCALE * (Wo bv)
__global__ void biasvec_kernel(const float* __restrict__ wk, const float* __restrict__ wo,
                               const float* __restrict__ bq, const float* __restrict__ bv,
                               float* __restrict__ a2, float* __restrict__ wobv) {
    const int i = blockIdx.x;
    const int t = threadIdx.x;          // 128 threads
    float s2 = 0.f, s3 = 0.f;
    for (int o = t; o < CH; o += 128) {
        s2 += wk[(size_t)o * CH + i] * bq[o];
        s3 += wo[(size_t)i * CH + o] * bv[o];
    }
    __shared__ float sh[2][128];
    sh[0][t] = s2; sh[1][t] = s3;
    __syncthreads();
    for (int o = 64; o > 0; o >>= 1) {
        if (t < o) {
            sh[0][t] += sh[0][t + o]; sh[1][t] += sh[1][t + o];
        }
        __syncthreads();
    }
    if (t == 0) {
        a2[i]   = sh[0][0];
        wobv[i] = sh[1][0] * WO_SCALE;
    }
}

// ---------------- mini GEMM for the 512x512x512 weight products ------------------
__global__ void __launch_bounds__(128)
mgemm_kernel(const f16* __restrict__ A, const f16* __restrict__ B, f16* __restrict__ C,
             size_t sA_batch, size_t sB_batch, size_t sC_batch)
{
    constexpr int BM = 64, BN = 64, BK = 64;
    constexpr int STAGES = 3;
    constexpr int LDS = BK + 8;         // 72
    constexpr int ASZ = BM * LDS;
    constexpr int BSZ = BN * LDS;
    extern __shared__ f16 smem[];
    f16* sA = smem;
    f16* sB = smem + STAGES * ASZ;

    const int tid  = threadIdx.x;
    const int lane = tid & 31;
    const int warp = tid >> 5;
    const int wm   = warp >> 1;         // 0..1 (32 rows)
    const int wn   = warp & 1;          // 0..1 (32 cols)
    const int bn0  = blockIdx.x * BN;
    const int bm0  = blockIdx.y * BM;
    const int z    = blockIdx.z;

    const f16* Ab = A + (size_t)z * sA_batch;
    const f16* Bb = B + (size_t)z * sB_batch;

    auto load_stage = [&](int stg, int kt) {
        const int ko = kt * BK;
        #pragma unroll
        for (int i = 0; i < 4; ++i) {
            const int q   = tid + i * 128;
            const int row = q >> 3;
            const int col = (q & 7) * 8;
            cp16(sA + stg * ASZ + row * LDS + col, Ab + (size_t)(bm0 + row) * CH + ko + col);
        }
        #pragma unroll
        for (int i = 0; i < 4; ++i) {
            const int q   = tid + i * 128;
            const int row = q >> 3;
            const int col = (q & 7) * 8;
            cp16(sB + stg * BSZ + row * LDS + col, Bb + (size_t)(bn0 + row) * CH + ko + col);
        }
        cp_commit();
    };

    const int nk = CH / BK;   // 8
    load_stage(0, 0);
    load_stage(1, 1);

    uint32_t acc[2][4][2];
    #pragma unroll
    for (int i = 0; i < 2; ++i)
        #pragma unroll
        for (int j = 0; j < 4; ++j) { acc[i][j][0] = 0u; acc[i][j][1] = 0u; }

    const int a_base = (wm * 32 + (lane & 15)) * LDS + (lane >> 4) * 8;
    const int b_base = (wn * 32 + (lane & 7) + ((lane >> 4) & 1) * 8) * LDS
                     + ((lane >> 3) & 1) * 8;

    int s_cur = 0, s_nxt2 = 2;
    for (int kt = 0; kt < nk; ++kt) {
        if (kt + 2 <= nk) cp_wait<1>(); else cp_wait<0>();
        __syncthreads();
        if (kt + 2 < nk) load_stage(s_nxt2, kt + 2);

        const f16* ca = sA + s_cur * ASZ;
        const f16* cb = sB + s_cur * BSZ;
        #pragma unroll
        for (int ks = 0; ks < 4; ++ks) {       // 4 k16 steps in BK=64
            uint32_t af[2][4];
            #pragma unroll
            for (int mf = 0; mf < 2; ++mf)
                ldsm4(af[mf][0], af[mf][1], af[mf][2], af[mf][3],
                      &ca[a_base + mf * 16 * LDS + ks * 16]);
            uint32_t bg[4][2];
            #pragma unroll
            for (int pr = 0; pr < 2; ++pr)
                ldsm4(bg[2 * pr][0], bg[2 * pr][1], bg[2 * pr + 1][0], bg[2 * pr + 1][1],
                      &cb[b_base + pr * 16 * LDS + ks * 16]);
            #pragma unroll
            for (int mf = 0; mf < 2; ++mf)
                #pragma unroll
                for (int nf = 0; nf < 4; ++nf)
                    mma_f16(acc[mf][nf], af[mf], bg[nf]);
        }
        s_cur  = (s_cur == STAGES - 1)  ? 0 : s_cur + 1;
        s_nxt2 = (s_nxt2 == STAGES - 1) ? 0 : s_nxt2 + 1;
    }

    f16* Cb = C + (size_t)z * sC_batch;
    const int r_base = bm0 + wm * 32 + (lane >> 2);
    const int c_base = bn0 + wn * 32 + ((lane & 3) << 1);
    #pragma unroll
    for (int mf = 0; mf < 2; ++mf) {
        #pragma unroll
        for (int nf = 0; nf < 4; ++nf) {
            const int r = r_base + mf * 16;
            const int c = c_base + nf * 8;
            *(__half2*)(Cb + (size_t)r * CH + c)       = *(const __half2*)&acc[mf][nf][0];
            *(__half2*)(Cb + (size_t)(r + 8) * CH + c) = *(const __half2*)&acc[mf][nf][1];
        }
    }
}

// ---------------- GEMM: C[m,n] = sum_k A[m,k]*B[n,k], f16 accum -----------------
// CTA tile 128x256 (BK=32); 8 warps of 64x64. 3-stage cp.async pipeline.
// EPI 1: f16 out, optional row bias (bias1 fp32, nullable)
// EPI 2: f16 out = exp(acc*scale + sw[c]) with sw[c] = SCALE_S * sum_k B[c][k]*bias2[k]
//        computed INLINE from B fragments (weighted colsum; bias2 = a2[512])
// EPI 5: fp32 out at [z][r][c]: acc * (1/colsum(B)) * WO_UNSCALE + bias1[r] + aux residual
template<int EPI>
__global__ void __launch_bounds__(256, 2)
gemm_kernel(const f16* __restrict__ A, const f16* __restrict__ B,
            void* __restrict__ Cout,
            int K, int lda, int ldb, int ldc,
            size_t sA_batch, size_t sB_batch, size_t sC_batch,
            const float* __restrict__ bias1, const float* __restrict__ bias2,
            const float* __restrict__ aux, float scale)
{
    constexpr int BM = 128, BN = 256, BK = 32;
    constexpr int STAGES = 3;
    constexpr int LDS = BK + 8;
    constexpr int ASZ = BM * LDS;
    constexpr int BSZ = BN * LDS;
    extern __shared__ f16 smem[];
    f16* sA = smem;
    f16* sB = smem + STAGES * ASZ;

    __shared__ float cs_sh[BN];   // column sums / sw values (EPI 2 & 5)

    const int tid  = threadIdx.x;
    const int lane = tid & 31;
    const int warp = tid >> 5;
    const int wm   = warp >> 2;
    const int wn   = warp & 3;
    const int bm0  = blockIdx.y * BM;
    const int bn0  = blockIdx.x * BN;
    const int z    = blockIdx.z;

    const f16* Ab = A + (size_t)z * sA_batch;
    const f16* Bb = B + (size_t)z * sB_batch;

    const int arow = tid >> 1;
    const int acol = (tid & 1) * 16;
    const int brow = tid >> 2;
    const int bcol = (tid & 3) * 8;

    const f16* gA = Ab + (size_t)(bm0 + arow) * lda + acol;
    const f16* gB = Bb + (size_t)(bn0 + brow) * ldb + bcol;
    f16* swA = sA + arow * LDS + acol;
    f16* swB = sB + brow * LDS + bcol;

    const int nk = K / BK;

    auto load_stage = [&](int stg, int kt) {
        const int ko = kt * BK;
        f16* dA = swA + stg * ASZ;
        f16* dB = swB + stg * BSZ;
        cp16(dA,     gA + ko);
        cp16(dA + 8, gA + ko + 8);
        #pragma unroll
        for (int i = 0; i < 4; ++i)
            cp16(dB + i * 64 * LDS, gB + (size_t)i * 64 * ldb + ko);
        cp_commit();
    };

    load_stage(0, 0);
    load_stage(1, 1);          // nk >= 16 always here

    uint32_t acc[4][8][2];
    #pragma unroll
    for (int i = 0; i < 4; ++i)
        #pragma unroll
        for (int j = 0; j < 8; ++j) { acc[i][j][0] = 0u; acc[i][j][1] = 0u; }

    float bsum[8];
    if (EPI == 5 || EPI == 2) {
        #pragma unroll
        for (int i = 0; i < 8; ++i) bsum[i] = 0.f;
    }

    const int a_base = (wm * 64 + (lane & 15)) * LDS + (lane >> 4) * 8;
    const int b_base = (wn * 64 + (lane & 7) + ((lane >> 4) & 1) * 8) * LDS
                     + ((lane >> 3) & 1) * 8;

    int s_cur = 0, s_nxt2 = 2;

    for (int kt = 0; kt < nk; ++kt) {
        if (kt + 2 <= nk) cp_wait<1>(); else cp_wait<0>();
        __syncthreads();

        if (kt + 2 < nk) load_stage(s_nxt2, kt + 2);

        const f16* ca = sA + s_cur * ASZ;
        const f16* cb = sB + s_cur * BSZ;
        #pragma unroll
        for (int ks = 0; ks < 2; ++ks) {
            uint32_t af[4][4];
            #pragma unroll
            for (int mf = 0; mf < 4; ++mf)
                ldsm4(af[mf][0], af[mf][1], af[mf][2], af[mf][3],
                      &ca[a_base + mf * 16 * LDS + ks * 16]);
            uint32_t bg[8][2];
            #pragma unroll
            for (int pr = 0; pr < 4; ++pr)
                ldsm4(bg[2 * pr][0], bg[2 * pr][1], bg[2 * pr + 1][0], bg[2 * pr + 1][1],
                      &cb[b_base + pr * 16 * LDS + ks * 16]);

            if (EPI == 5 && wm == 0) {
                // unweighted column sums of B (for softmax denominator)
                #pragma unroll
                for (int nf = 0; nf < 8; ++nf)
                    bsum[nf] += hsum2(bg[nf][0]) + hsum2(bg[nf][1]);
            }
            if (EPI == 2 && wm == 0) {
                // a2-weighted column sums of B: reg0 holds k = kb+{0,1},
                // reg1 holds k = kb+{8,9}, kb = kt*32 + ks*16 + (lane&3)*2
                const int kb = kt * BK + ks * 16 + ((lane & 3) << 1);
                const float2 w0 = *(const float2*)(bias2 + kb);
                const float2 w8 = *(const float2*)(bias2 + kb + 8);
                #pragma unroll
                for (int nf = 0; nf < 8; ++nf) {
                    float2 l0 = __half22float2(*(const __half2*)&bg[nf][0]);
                    float2 l1 = __half22float2(*(const __half2*)&bg[nf][1]);
                    bsum[nf] += l0.x * w0.x + l0.y * w0.y + l1.x * w8.x + l1.y * w8.y;
                }
            }

            #pragma unroll
            for (int mf = 0; mf < 4; ++mf)
                #pragma unroll
                for (int nf = 0; nf < 8; ++nf)
                    mma_f16(acc[mf][nf], af[mf], bg[nf]);
        }

        s_cur  = (s_cur == STAGES - 1)  ? 0 : s_cur + 1;
        s_nxt2 = (s_nxt2 == STAGES - 1) ? 0 : s_nxt2 + 1;
    }

    if (EPI == 5 || EPI == 2) {
        if (wm == 0) {
            #pragma unroll
            for (int nf = 0; nf < 8; ++nf) {
                float v = bsum[nf];
                v += __shfl_xor_sync(0xffffffffu, v, 1);
                v += __shfl_xor_sync(0xffffffffu, v, 2);
                if ((lane & 3) == 0) {
                    const int idx = wn * 64 + (nf >> 1) * 16 + (nf & 1) * 8 + (lane >> 2);
                    cs_sh[idx] = (EPI == 2) ? v * SCALE_S : v;
                }
            }
        }
        __syncthreads();
    }

    const int r_base = bm0 + wm * 64 + (lane >> 2);
    const int c_base = bn0 + wn * 64 + ((lane & 3) << 1);

    #pragma unroll
    for (int mf = 0; mf < 4; ++mf) {
        #pragma unroll
        for (int nf = 0; nf < 8; ++nf) {
            const int r = r_base + mf * 16;
            const int c = c_base + nf * 8;
            float2 f0 = __half22float2(*(const __half2*)&acc[mf][nf][0]); // (r, c/c+1)
            float2 f1 = __half22float2(*(const __half2*)&acc[mf][nf][1]); // (r+8, c/c+1)

            if (EPI == 1) {
                f16* outp = (f16*)Cout + (size_t)z * sC_batch;
                const float rb0 = bias1 ? bias1[r] : 0.f;
                const float rb1 = bias1 ? bias1[r + 8] : 0.f;
                *(__half2*)(outp + (size_t)r * ldc + c) =
                    __floats2half2_rn(f0.x + rb0, f0.y + rb0);
                *(__half2*)(outp + (size_t)(r + 8) * ldc + c) =
                    __floats2half2_rn(f1.x + rb1, f1.y + rb1);
            } else if (EPI == 2) {
                f16* outp = (f16*)Cout + (size_t)z * sC_batch;
                const float sw0 = cs_sh[c - bn0];
                const float sw1 = cs_sh[c + 1 - bn0];
                *(__half2*)(outp + (size_t)r * ldc + c) =
                    __floats2half2_rn(__expf(f0.x * scale + sw0),
                                      __expf(f0.y * scale + sw1));
                *(__half2*)(outp + (size_t)(r + 8) * ldc + c) =
                    __floats2half2_rn(__expf(f1.x * scale + sw0),
                                      __expf(f1.y * scale + sw1));
            } else {   // EPI == 5 : final fp32 out + residual, column-normalized
                float* outp = (float*)Cout;
                const float inv0 = WO_UNSCALE / cs_sh[c - bn0];
                const float inv1 = WO_UNSCALE / cs_sh[c + 1 - bn0];
                const size_t i0 = (size_t)z * (CH * HWDIM) + (size_t)r * HWDIM + c;
                const size_t i1 = i0 + 8 * HWDIM;
                const float br0 = bias1 ? bias1[r] : 0.f;
                const float br1 = bias1 ? bias1[r + 8] : 0.f;
                const float2 x0 = *(const float2*)(aux + i0);
                const float2 x1 = *(const float2*)(aux + i1);
                *(float2*)(outp + i0) = make_float2(f0.x * inv0 + br0 + x0.x,
                                                    f0.y * inv1 + br0 + x0.y);
                *(float2*)(outp + i1) = make_float2(f1.x * inv0 + br1 + x1.x,
                                                    f1.y * inv1 + br1 + x1.y);
            }
        }
    }
}

// ---------------- launch -----------------------------------------------------------
static constexpr int GEMM_SMEM  = 3 * (128 * 40 + 256 * 40) * (int)sizeof(f16); // 92160
static constexpr int MGEMM_SMEM = 3 * (64 * 72 + 64 * 72) * (int)sizeof(f16);   // 55296

extern "C" void kernel_launch(void* const* d_in, const int* in_sizes, int n_in,
                              void* d_out, int out_size)
{
    (void)in_sizes; (void)n_in; (void)out_size;
    const float* x  = (const float*)d_in[0];
    const float* Wq = (const float*)d_in[1];
    const float* bq = (const float*)d_in[2];
    const float* Wk = (const float*)d_in[3];
    const float* bk = (const float*)d_in[4];
    const float* Wv = (const float*)d_in[5];
    const float* bv = (const float*)d_in[6];
    const float* Wo = (const float*)d_in[7];
    const float* bo = (const float*)d_in[8];
    (void)bk;
    float* out = (float*)d_out;

    f16 *pW, *pM, *pXT, *pT, *pU, *pP;
    float *pA2, *pWOBV;
    cudaGetSymbolAddress((void**)&pW,   g_W);
    cudaGetSymbolAddress((void**)&pM,   g_M);
    cudaGetSymbolAddress((void**)&pXT,  g_XT);
    cudaGetSymbolAddress((void**)&pT,   g_T);
    cudaGetSymbolAddress((void**)&pU,   g_U);
    cudaGetSymbolAddress((void**)&pP,   g_P);
    cudaGetSymbolAddress((void**)&pA2,  g_A2);
    cudaGetSymbolAddress((void**)&pWOBV,g_WOBV);

    cudaFuncSetAttribute(gemm_kernel<1>, cudaFuncAttributeMaxDynamicSharedMemorySize, GEMM_SMEM);
    cudaFuncSetAttribute(gemm_kernel<2>, cudaFuncAttributeMaxDynamicSharedMemorySize, GEMM_SMEM);
    cudaFuncSetAttribute(gemm_kernel<5>, cudaFuncAttributeMaxDynamicSharedMemorySize, GEMM_SMEM);
    cudaFuncSetAttribute(mgemm_kernel,   cudaFuncAttributeMaxDynamicSharedMemorySize, MGEMM_SMEM);

    // prep
    convert_w_kernel<<<dim3(16, 16, 4), dim3(32, 32)>>>(Wq, Wk, Wv, Wo, pW);
    xt_kernel<<<dim3(HWDIM / 64, CH / 64, BATCH), 256>>>(x, pXT);
    biasvec_kernel<<<CH, 128>>>(Wk, Wo, bq, bv, pA2, pWOBV);

    // MsT = Wk^T Wq (z=0), Mo = Wo_s Wv (z=1): M=N=K=512, 64x64 tiles
    mgemm_kernel<<<dim3(8, 8, 2), 128, MGEMM_SMEM>>>(
        pW, pW + CH * CH, pM,
        (size_t)2 * CH * CH, (size_t)2 * CH * CH, (size_t)CH * CH);

    // T = X * Ms : M=32768, N=512, K=512  (B = MsT)
    gemm_kernel<1><<<dim3(2, NALL / 128, 1), 256, GEMM_SMEM>>>(
        pXT, pM, pT, CH, CH, CH, CH, 0, 0, 0,
        nullptr, nullptr, nullptr, 1.f);

    // U = Mo * X^T (+wobv rows) : M=512, N=32768, K=512 -> [r][token]
    gemm_kernel<1><<<dim3(NALL / 256, 4, 1), 256, GEMM_SMEM>>>(
        pM + CH * CH, pXT, pU, CH, CH, CH, NALL, 0, 0, 0,
        pWOBV, nullptr, nullptr, 1.f);

    // P_b = exp(scale*T_b X_b^T + sw_j) : per batch M=N=1024, K=512
    // (sw_j computed inline from the B=XT fragments, weighted by a2)
    gemm_kernel<2><<<dim3(4, 8, BATCH), 256, GEMM_SMEM>>>(
        pT, pXT, pP, CH, CH, CH, HWDIM,
        (size_t)HWDIM * CH, (size_t)HWDIM * CH, (size_t)HWDIM * HWDIM,
        nullptr, pA2, nullptr, SCALE_S);

    // O_b = U_b P_b^T / colsum + bo + x : M=512, N=1024, K=1024 per batch
    gemm_kernel<5><<<dim3(4, 4, BATCH), 256, GEMM_SMEM>>>(
        pU, pP, out, HWDIM, NALL, HWDIM, HWDIM,
        (size_t)HWDIM, (size_t)HWDIM * HWDIM, 0,
        bo, nullptr, x, 1.f);
}

// round 16
// speedup vs baseline: 1.0371x; 1.0371x over previous
#include <cuda_runtime.h>
#include <cuda_fp16.h>
#include <cstdint>

using f16 = __half;
#define DEVINLINE __device__ __forceinline__

static constexpr int CH    = 512;
static constexpr int HWDIM = 1024;
static constexpr int BATCH = 32;
static constexpr int NALL  = BATCH * HWDIM;   // 32768

static constexpr float WO_SCALE   = 4096.f;
static constexpr float WO_UNSCALE = 1.f / 4096.f;
static constexpr float SCALE_S    = 0.04419417382415922f;  // 512^-0.5

// ---------------- scratch ----------------------------------------------------
// g_W slots: 0=WkT, 1=WqT, 2=Wo_s(row-major, x4096), 3=WvT
__device__ f16   g_W [4 * CH * CH];
__device__ f16   g_M [2 * CH * CH];                  // 0=MsT, 1=Mo
__device__ f16   g_XT[(size_t)NALL * CH];            // [token][c]
__device__ f16   g_T [(size_t)NALL * CH];            // [token][c']  = X*Ms
__device__ f16   g_U [(size_t)CH * NALL];            // [r][token]   = Mo*X^T
__device__ f16   g_P [(size_t)BATCH * HWDIM * HWDIM];
__device__ float g_A2[CH], g_WOBV[CH];
__device__ float g_SW[NALL];

// ---------------- helpers ------------------------------------------------------
DEVINLINE void ldsm4(uint32_t& r0, uint32_t& r1, uint32_t& r2, uint32_t& r3,
                     const f16* p) {
    uint32_t addr = (uint32_t)__cvta_generic_to_shared(p);
    asm volatile("ldmatrix.sync.aligned.m8n8.x4.shared.b16 {%0,%1,%2,%3}, [%4];"
                 : "=r"(r0), "=r"(r1), "=r"(r2), "=r"(r3) : "r"(addr));
}

DEVINLINE void mma_f16(uint32_t c[2], const uint32_t a[4], const uint32_t b[2]) {
    asm volatile("mma.sync.aligned.m16n8k16.row.col.f16.f16.f16.f16 "
                 "{%0,%1},{%2,%3,%4,%5},{%6,%7},{%0,%1};"
                 : "+r"(c[0]), "+r"(c[1])
                 : "r"(a[0]), "r"(a[1]), "r"(a[2]), "r"(a[3]),
                   "r"(b[0]), "r"(b[1]));
}

DEVINLINE void cp16(f16* dst, const f16* src) {
    uint32_t d = (uint32_t)__cvta_generic_to_shared(dst);
    asm volatile("cp.async.cg.shared.global [%0], [%1], 16;" :: "r"(d), "l"(src));
}
DEVINLINE void cp_commit() { asm volatile("cp.async.commit_group;"); }
template<int N> DEVINLINE void cp_wait() {
    asm volatile("cp.async.wait_group %0;" :: "n"(N));
}

DEVINLINE float hsum2(uint32_t h) {
    float2 f = __half22float2(*reinterpret_cast<const __half2*>(&h));
    return f.x + f.y;
}

// ---------------- prep kernels ---------------------------------------------------
// z=0: WkT<-Wk  z=1: WqT<-Wq  z=2: Wo_s copy(x4096)  z=3: WvT<-Wv
__global__ void convert_w_kernel(const float* __restrict__ wq, const float* __restrict__ wk,
                                 const float* __restrict__ wv, const float* __restrict__ wo,
                                 f16* __restrict__ W) {
    __shared__ float t[32][33];
    const int z = blockIdx.z;
    const float* src = (z == 0) ? wk : (z == 1) ? wq : (z == 2) ? wo : wv;
    f16* dst = W + (size_t)z * CH * CH;
    const int r0 = blockIdx.y * 32, c0 = blockIdx.x * 32;
    const int tx = threadIdx.x, ty = threadIdx.y;
    if (z == 2) {
        dst[(size_t)(r0 + ty) * CH + c0 + tx] =
            __float2half(src[(size_t)(r0 + ty) * CH + c0 + tx] * WO_SCALE);
    } else {
        t[ty][tx] = src[(size_t)(r0 + ty) * CH + c0 + tx];
        __syncthreads();
        dst[(size_t)(c0 + ty) * CH + r0 + tx] = __float2half(t[tx][ty]);
    }
}

// x [B][C][HW] fp32 -> XT [B*HW][C] f16.  64x64 tiles, float4 loads,
// pad-65 smem (conflict-free column reads), uint4 f16 stores.
__global__ void __launch_bounds__(256)
xt_kernel(const float* __restrict__ x, f16* __restrict__ XT) {
    __shared__ float tile[64][65];
    const int b  = blockIdx.z;
    const int s0 = blockIdx.x * 64;
    const int c0 = blockIdx.y * 64;
    const int t  = threadIdx.x;
    const int r  = t >> 4;             // 0..15
    const int q4 = (t & 15) * 4;       // float col (0,4,...,60)
    #pragma unroll
    for (int i = 0; i < 4; ++i) {
        const int row = r + i * 16;
        const float4 v = *(const float4*)(x + ((size_t)b * CH + c0 + row) * HWDIM + s0 + q4);
        tile[row][q4]     = v.x;
        tile[row][q4 + 1] = v.y;
        tile[row][q4 + 2] = v.z;
        tile[row][q4 + 3] = v.w;
    }
    __syncthreads();
    #pragma unroll
    for (int i = 0; i < 2; ++i) {
        const int q  = t + i * 256;
        const int j  = q >> 3;          // token within tile (0..63)
        const int cc = (q & 7) * 8;     // channel chunk
        f16 buf[8];
        #pragma unroll
        for (int e = 0; e < 8; ++e)
            buf[e] = __float2half(tile[cc + e][j]);
        *(uint4*)(XT + ((size_t)b * HWDIM + s0 + j) * CH + c0 + cc) = *(uint4*)buf;
    }
}

// a2 = Wk^T bq, wobv = WO_SCALE * (Wo bv)
__global__ void biasvec_kernel(const float* __restrict__ wk, const float* __restrict__ wo,
                               const float* __restrict__ bq, const float* __restrict__ bv,
                               float* __restrict__ a2, float* __restrict__ wobv) {
    const int i = blockIdx.x;
    const int t = threadIdx.x;          // 128 threads
    float s2 = 0.f, s3 = 0.f;
    for (int o = t; o < CH; o += 128) {
        s2 += wk[(size_t)o * CH + i] * bq[o];
        s3 += wo[(size_t)i * CH + o] * bv[o];
    }
    __shared__ float sh[2][128];
    sh[0][t] = s2; sh[1][t] = s3;
    __syncthreads();
    for (int o = 64; o > 0; o >>= 1) {
        if (t < o) {
            sh[0][t] += sh[0][t + o]; sh[1][t] += sh[1][t + o];
        }
        __syncthreads();
    }
    if (t == 0) {
        a2[i]   = sh[0][0];
        wobv[i] = sh[1][0] * WO_SCALE;
    }
}

// sw[t] = SCALE_S * (XT[t] . a2)
__global__ void uw_kernel(const f16* __restrict__ XT,
                          const float* __restrict__ a2,
                          float* __restrict__ sw) {
    const int tok  = blockIdx.x * 8 + (threadIdx.x >> 5);
    const int lane = threadIdx.x & 31;
    const __half2* xr = (const __half2*)(XT + (size_t)tok * CH);
    const float2* p2 = (const float2*)a2;
    float s2 = 0.f;
    #pragma unroll
    for (int j = lane; j < 256; j += 32) {
        float2 xv = __half22float2(xr[j]);
        float2 v2 = p2[j];
        s2 += xv.x * v2.x + xv.y * v2.y;
    }
    #pragma unroll
    for (int o = 16; o > 0; o >>= 1)
        s2 += __shfl_xor_sync(0xffffffffu, s2, o);
    if (lane == 0) sw[tok] = SCALE_S * s2;
}

// ---------------- mini GEMM for the 512x512x512 weight products ------------------
__global__ void __launch_bounds__(128)
mgemm_kernel(const f16* __restrict__ A, const f16* __restrict__ B, f16* __restrict__ C,
             size_t sA_batch, size_t sB_batch, size_t sC_batch)
{
    constexpr int BM = 64, BN = 64, BK = 64;
    constexpr int STAGES = 3;
    constexpr int LDS = BK + 8;         // 72
    constexpr int ASZ = BM * LDS;
    constexpr int BSZ = BN * LDS;
    extern __shared__ f16 smem[];
    f16* sA = smem;
    f16* sB = smem + STAGES * ASZ;

    const int tid  = threadIdx.x;
    const int lane = tid & 31;
    const int warp = tid >> 5;
    const int wm   = warp >> 1;         // 0..1 (32 rows)
    const int wn   = warp & 1;          // 0..1 (32 cols)
    const int bn0  = blockIdx.x * BN;
    const int bm0  = blockIdx.y * BM;
    const int z    = blockIdx.z;

    const f16* Ab = A + (size_t)z * sA_batch;
    const f16* Bb = B + (size_t)z * sB_batch;

    auto load_stage = [&](int stg, int kt) {
        const int ko = kt * BK;
        #pragma unroll
        for (int i = 0; i < 4; ++i) {
            const int q   = tid + i * 128;
            const int row = q >> 3;
            const int col = (q & 7) * 8;
            cp16(sA + stg * ASZ + row * LDS + col, Ab + (size_t)(bm0 + row) * CH + ko + col);
        }
        #pragma unroll
        for (int i = 0; i < 4; ++i) {
            const int q   = tid + i * 128;
            const int row = q >> 3;
            const int col = (q & 7) * 8;
            cp16(sB + stg * BSZ + row * LDS + col, Bb + (size_t)(bn0 + row) * CH + ko + col);
        }
        cp_commit();
    };

    const int nk = CH / BK;   // 8
    load_stage(0, 0);
    load_stage(1, 1);

    uint32_t acc[2][4][2];
    #pragma unroll
    for (int i = 0; i < 2; ++i)
        #pragma unroll
        for (int j = 0; j < 4; ++j) { acc[i][j][0] = 0u; acc[i][j][1] = 0u; }

    const int a_base = (wm * 32 + (lane & 15)) * LDS + (lane >> 4) * 8;
    const int b_base = (wn * 32 + (lane & 7) + ((lane >> 4) & 1) * 8) * LDS
                     + ((lane >> 3) & 1) * 8;

    int s_cur = 0, s_nxt2 = 2;
    for (int kt = 0; kt < nk; ++kt) {
        if (kt + 2 <= nk) cp_wait<1>(); else cp_wait<0>();
        __syncthreads();
        if (kt + 2 < nk) load_stage(s_nxt2, kt + 2);

        const f16* ca = sA + s_cur * ASZ;
        const f16* cb = sB + s_cur * BSZ;
        #pragma unroll
        for (int ks = 0; ks < 4; ++ks) {       // 4 k16 steps in BK=64
            uint32_t af[2][4];
            #pragma unroll
            for (int mf = 0; mf < 2; ++mf)
                ldsm4(af[mf][0], af[mf][1], af[mf][2], af[mf][3],
                      &ca[a_base + mf * 16 * LDS + ks * 16]);
            uint32_t bg[4][2];
            #pragma unroll
            for (int pr = 0; pr < 2; ++pr)
                ldsm4(bg[2 * pr][0], bg[2 * pr][1], bg[2 * pr + 1][0], bg[2 * pr + 1][1],
                      &cb[b_base + pr * 16 * LDS + ks * 16]);
            #pragma unroll
            for (int mf = 0; mf < 2; ++mf)
                #pragma unroll
                for (int nf = 0; nf < 4; ++nf)
                    mma_f16(acc[mf][nf], af[mf], bg[nf]);
        }
        s_cur  = (s_cur == STAGES - 1)  ? 0 : s_cur + 1;
        s_nxt2 = (s_nxt2 == STAGES - 1) ? 0 : s_nxt2 + 1;
    }

    f16* Cb = C + (size_t)z * sC_batch;
    const int r_base = bm0 + wm * 32 + (lane >> 2);
    const int c_base = bn0 + wn * 32 + ((lane & 3) << 1);
    #pragma unroll
    for (int mf = 0; mf < 2; ++mf) {
        #pragma unroll
        for (int nf = 0; nf < 4; ++nf) {
            const int r = r_base + mf * 16;
            const int c = c_base + nf * 8;
            *(__half2*)(Cb + (size_t)r * CH + c)       = *(const __half2*)&acc[mf][nf][0];
            *(__half2*)(Cb + (size_t)(r + 8) * CH + c) = *(const __half2*)&acc[mf][nf][1];
        }
    }
}

// ---------------- GEMM: C[m,n] = sum_k A[m,k]*B[n,k], f16 accum -----------------
// CTA tile 128x256 (BK=32); 8 warps of 64x64. 3-stage cp.async pipeline.
// EPI 1: f16 out, optional row bias (bias1 fp32, nullable)
// EPI 2: f16 out = exp(acc*scale + bias2[z*1024+c])
// EPI 5: fp32 out at [z][r][c]: acc * (1/colsum(B)) * WO_UNSCALE + bias1[r] + aux residual
template<int EPI>
__global__ void __launch_bounds__(256, 2)
gemm_kernel(const f16* __restrict__ A, const f16* __restrict__ B,
            void* __restrict__ Cout,
            int K, int lda, int ldb, int ldc,
            size_t sA_batch, size_t sB_batch, size_t sC_batch,
            const float* __restrict__ bias1, const float* __restrict__ bias2,
            const float* __restrict__ aux, float scale)
{
    constexpr int BM = 128, BN = 256, BK = 32;
    constexpr int STAGES = 3;
    constexpr int LDS = BK + 8;
    constexpr int ASZ = BM * LDS;
    constexpr int BSZ = BN * LDS;
    extern __shared__ f16 smem[];
    f16* sA = smem;
    f16* sB = smem + STAGES * ASZ;

    __shared__ float cs_sh[BN];   // column sums (EPI 5)

    const int tid  = threadIdx.x;
    const int lane = tid & 31;
    const int warp = tid >> 5;
    const int wm   = warp >> 2;
    const int wn   = warp & 3;
    const int bm0  = blockIdx.y * BM;
    const int bn0  = blockIdx.x * BN;
    const int z    = blockIdx.z;

    const f16* Ab = A + (size_t)z * sA_batch;
    const f16* Bb = B + (size_t)z * sB_batch;

    const int arow = tid >> 1;
    const int acol = (tid & 1) * 16;
    const int brow = tid >> 2;
    const int bcol = (tid & 3) * 8;

    const f16* gA = Ab + (size_t)(bm0 + arow) * lda + acol;
    const f16* gB = Bb + (size_t)(bn0 + brow) * ldb + bcol;
    f16* swA = sA + arow * LDS + acol;
    f16* swB = sB + brow * LDS + bcol;

    const int nk = K / BK;

    auto load_stage = [&](int stg, int kt) {
        const int ko = kt * BK;
        f16* dA = swA + stg * ASZ;
        f16* dB = swB + stg * BSZ;
        cp16(dA,     gA + ko);
        cp16(dA + 8, gA + ko + 8);
        #pragma unroll
        for (int i = 0; i < 4; ++i)
            cp16(dB + i * 64 * LDS, gB + (size_t)i * 64 * ldb + ko);
        cp_commit();
    };

    load_stage(0, 0);
    load_stage(1, 1);          // nk >= 16 always here

    uint32_t acc[4][8][2];
    #pragma unroll
    for (int i = 0; i < 4; ++i)
        #pragma unroll
        for (int j = 0; j < 8; ++j) { acc[i][j][0] = 0u; acc[i][j][1] = 0u; }

    float bsum[8];
    if (EPI == 5) {
        #pragma unroll
        for (int i = 0; i < 8; ++i) bsum[i] = 0.f;
    }

    const int a_base = (wm * 64 + (lane & 15)) * LDS + (lane >> 4) * 8;
    const int b_base = (wn * 64 + (lane & 7) + ((lane >> 4) & 1) * 8) * LDS
                     + ((lane >> 3) & 1) * 8;

    int s_cur = 0, s_nxt2 = 2;

    for (int kt = 0; kt < nk; ++kt) {
        if (kt + 2 <= nk) cp_wait<1>(); else cp_wait<0>();
        __syncthreads();

        if (kt + 2 < nk) load_stage(s_nxt2, kt + 2);

        const f16* ca = sA + s_cur * ASZ;
        const f16* cb = sB + s_cur * BSZ;
        #pragma unroll
        for (int ks = 0; ks < 2; ++ks) {
            uint32_t af[4][4];
            #pragma unroll
            for (int mf = 0; mf < 4; ++mf)
                ldsm4(af[mf][0], af[mf][1], af[mf][2], af[mf][3],
                      &ca[a_base + mf * 16 * LDS + ks * 16]);
            uint32_t bg[8][2];
            #pragma unroll
            for (int pr = 0; pr < 4; ++pr)
                ldsm4(bg[2 * pr][0], bg[2 * pr][1], bg[2 * pr + 1][0], bg[2 * pr + 1][1],
                      &cb[b_base + pr * 16 * LDS + ks * 16]);

            if (EPI == 5 && wm == 0) {
                // per-lane partial column sums of B (rows of B = C columns)
                #pragma unroll
                for (int nf = 0; nf < 8; ++nf)
                    bsum[nf] += hsum2(bg[nf][0]) + hsum2(bg[nf][1]);
            }

            #pragma unroll
            for (int mf = 0; mf < 4; ++mf)
                #pragma unroll
                for (int nf = 0; nf < 8; ++nf)
                    mma_f16(acc[mf][nf], af[mf], bg[nf]);
        }

        s_cur  = (s_cur == STAGES - 1)  ? 0 : s_cur + 1;
        s_nxt2 = (s_nxt2 == STAGES - 1) ? 0 : s_nxt2 + 1;
    }

    if (EPI == 5) {
        if (wm == 0) {
            #pragma unroll
            for (int nf = 0; nf < 8; ++nf) {
                float v = bsum[nf];
                v += __shfl_xor_sync(0xffffffffu, v, 1);
                v += __shfl_xor_sync(0xffffffffu, v, 2);
                if ((lane & 3) == 0)
                    cs_sh[wn * 64 + (nf >> 1) * 16 + (nf & 1) * 8 + (lane >> 2)] = v;
            }
        }
        __syncthreads();
    }

    const int r_base = bm0 + wm * 64 + (lane >> 2);
    const int c_base = bn0 + wn * 64 + ((lane & 3) << 1);

    #pragma unroll
    for (int mf = 0; mf < 4; ++mf) {
        #pragma unroll
        for (int nf = 0; nf < 8; ++nf) {
            const int r = r_base + mf * 16;
            const int c = c_base + nf * 8;
            float2 f0 = __half22float2(*(const __half2*)&acc[mf][nf][0]); // (r, c/c+1)
            float2 f1 = __half22float2(*(const __half2*)&acc[mf][nf][1]); // (r+8, c/c+1)

            if (EPI == 1) {
                f16* outp = (f16*)Cout + (size_t)z * sC_batch;
                const float rb0 = bias1 ? bias1[r] : 0.f;
                const float rb1 = bias1 ? bias1[r + 8] : 0.f;
                *(__half2*)(outp + (size_t)r * ldc + c) =
                    __floats2half2_rn(f0.x + rb0, f0.y + rb0);
                *(__half2*)(outp + (size_t)(r + 8) * ldc + c) =
                    __floats2half2_rn(f1.x + rb1, f1.y + rb1);
            } else if (EPI == 2) {
                f16* outp = (f16*)Cout + (size_t)z * sC_batch;
                const float sw0 = bias2[z * HWDIM + c];
                const float sw1 = bias2[z * HWDIM + c + 1];
                *(__half2*)(outp + (size_t)r * ldc + c) =
                    __floats2half2_rn(__expf(f0.x * scale + sw0),
                                      __expf(f0.y * scale + sw1));
                *(__half2*)(outp + (size_t)(r + 8) * ldc + c) =
                    __floats2half2_rn(__expf(f1.x * scale + sw0),
                                      __expf(f1.y * scale + sw1));
            } else {   // EPI == 5 : final fp32 out + residual, column-normalized
                float* outp = (float*)Cout;
                const float inv0 = WO_UNSCALE / cs_sh[c - bn0];
                const float inv1 = WO_UNSCALE / cs_sh[c + 1 - bn0];
                const size_t i0 = (size_t)z * (CH * HWDIM) + (size_t)r * HWDIM + c;
                const size_t i1 = i0 + 8 * HWDIM;
                const float br0 = bias1 ? bias1[r] : 0.f;
                const float br1 = bias1 ? bias1[r + 8] : 0.f;
                const float2 x0 = *(const float2*)(aux + i0);
                const float2 x1 = *(const float2*)(aux + i1);
                *(float2*)(outp + i0) = make_float2(f0.x * inv0 + br0 + x0.x,
                                                    f0.y * inv1 + br0 + x0.y);
                *(float2*)(outp + i1) = make_float2(f1.x * inv0 + br1 + x1.x,
                                                    f1.y * inv1 + br1 + x1.y);
            }
        }
    }
}

// ---------------- launch -----------------------------------------------------------
static constexpr int GEMM_SMEM  = 3 * (128 * 40 + 256 * 40) * (int)sizeof(f16); // 92160
static constexpr int MGEMM_SMEM = 3 * (64 * 72 + 64 * 72) * (int)sizeof(f16);   // 55296

extern "C" void kernel_launch(void* const* d_in, const int* in_sizes, int n_in,
                              void* d_out, int out_size)
{
    (void)in_sizes; (void)n_in; (void)out_size;
    const float* x  = (const float*)d_in[0];
    const float* Wq = (const float*)d_in[1];
    const float* bq = (const float*)d_in[2];
    const float* Wk = (const float*)d_in[3];
    const float* bk = (const float*)d_in[4];
    const float* Wv = (const float*)d_in[5];
    const float* bv = (const float*)d_in[6];
    const float* Wo = (const float*)d_in[7];
    const float* bo = (const float*)d_in[8];
    (void)bk;
    float* out = (float*)d_out;

    f16 *pW, *pM, *pXT, *pT, *pU, *pP;
    float *pA2, *pWOBV, *pSW;
    cudaGetSymbolAddress((void**)&pW,   g_W);
    cudaGetSymbolAddress((void**)&pM,   g_M);
    cudaGetSymbolAddress((void**)&pXT,  g_XT);
    cudaGetSymbolAddress((void**)&pT,   g_T);
    cudaGetSymbolAddress((void**)&pU,   g_U);
    cudaGetSymbolAddress((void**)&pP,   g_P);
    cudaGetSymbolAddress((void**)&pA2,  g_A2);
    cudaGetSymbolAddress((void**)&pWOBV,g_WOBV);
    cudaGetSymbolAddress((void**)&pSW,  g_SW);

    cudaFuncSetAttribute(gemm_kernel<1>, cudaFuncAttributeMaxDynamicSharedMemorySize, GEMM_SMEM);
    cudaFuncSetAttribute(gemm_kernel<2>, cudaFuncAttributeMaxDynamicSharedMemorySize, GEMM_SMEM);
    cudaFuncSetAttribute(gemm_kernel<5>, cudaFuncAttributeMaxDynamicSharedMemorySize, GEMM_SMEM);
    cudaFuncSetAttribute(mgemm_kernel,   cudaFuncAttributeMaxDynamicSharedMemorySize, MGEMM_SMEM);

    // prep
    convert_w_kernel<<<dim3(16, 16, 4), dim3(32, 32)>>>(Wq, Wk, Wv, Wo, pW);
    xt_kernel<<<dim3(HWDIM / 64, CH / 64, BATCH), 256>>>(x, pXT);
    biasvec_kernel<<<CH, 128>>>(Wk, Wo, bq, bv, pA2, pWOBV);
    uw_kernel<<<NALL / 8, 256>>>(pXT, pA2, pSW);

    // MsT = Wk^T Wq (z=0), Mo = Wo_s Wv (z=1): M=N=K=512, 64x64 tiles
    mgemm_kernel<<<dim3(8, 8, 2), 128, MGEMM_SMEM>>>(
        pW, pW + CH * CH, pM,
        (size_t)2 * CH * CH, (size_t)2 * CH * CH, (size_t)CH * CH);

    // T = X * Ms : M=32768, N=512, K=512  (B = MsT)
    gemm_kernel<1><<<dim3(2, NALL / 128, 1), 256, GEMM_SMEM>>>(
        pXT, pM, pT, CH, CH, CH, CH, 0, 0, 0,
        nullptr, nullptr, nullptr, 1.f);

    // U = Mo * X^T (+wobv rows) : M=512, N=32768, K=512 -> [r][token]
    gemm_kernel<1><<<dim3(NALL / 256, 4, 1), 256, GEMM_SMEM>>>(
        pM + CH * CH, pXT, pU, CH, CH, CH, NALL, 0, 0, 0,
        pWOBV, nullptr, nullptr, 1.f);

    // P_b = exp(scale*T_b X_b^T + sw_j) : per batch M=N=1024, K=512
    gemm_kernel<2><<<dim3(4, 8, BATCH), 256, GEMM_SMEM>>>(
        pT, pXT, pP, CH, CH, CH, HWDIM,
        (size_t)HWDIM * CH, (size_t)HWDIM * CH, (size_t)HWDIM * HWDIM,
        nullptr, pSW, nullptr, SCALE_S);

    // O_b = U_b P_b^T / colsum + bo + x : M=512, N=1024, K=1024 per batch
    gemm_kernel<5><<<dim3(4, 4, BATCH), 256, GEMM_SMEM>>>(
        pU, pP, out, HWDIM, NALL, HWDIM, HWDIM,
        (size_t)HWDIM, (size_t)HWDIM * HWDIM, 0,
        bo, nullptr, x, 1.f);
}

// round 17
// speedup vs baseline: 1.0517x; 1.0141x over previous
#include <cuda_runtime.h>
#include <cuda_fp16.h>
#include <cstdint>

using f16 = __half;
#define DEVINLINE __device__ __forceinline__

static constexpr int CH    = 512;
static constexpr int HWDIM = 1024;
static constexpr int BATCH = 32;
static constexpr int NALL  = BATCH * HWDIM;   // 32768

static constexpr float WO_SCALE   = 4096.f;
static constexpr float WO_UNSCALE = 1.f / 4096.f;
static constexpr float SCALE_S    = 0.04419417382415922f;  // 512^-0.5

// ---------------- scratch ----------------------------------------------------
// g_W slots: 0=WkT, 1=WqT, 2=Wo_s(row-major, x4096), 3=WvT
__device__ f16   g_W [4 * CH * CH];
__device__ f16   g_M [2 * CH * CH];                  // 0=MsT, 1=Mo
__device__ f16   g_XT[(size_t)NALL * CH];            // [token][c]
__device__ f16   g_T [(size_t)NALL * CH];            // [token][c']  = X*Ms
__device__ f16   g_U [(size_t)CH * NALL];            // [r][token]   = Mo*X^T
__device__ f16   g_P [(size_t)BATCH * HWDIM * HWDIM];
__device__ float g_A2[CH], g_WOBV[CH];
__device__ float g_SW[NALL];

// ---------------- side stream + events (host resources only; created once) ----
static cudaStream_t g_s2;
static cudaEvent_t  g_evRoot, g_evXT, g_evM, g_evSW;
namespace {
struct StreamInit {
    StreamInit() {
        cudaStreamCreateWithFlags(&g_s2, cudaStreamNonBlocking);
        cudaEventCreateWithFlags(&g_evRoot, cudaEventDisableTiming);
        cudaEventCreateWithFlags(&g_evXT,   cudaEventDisableTiming);
        cudaEventCreateWithFlags(&g_evM,    cudaEventDisableTiming);
        cudaEventCreateWithFlags(&g_evSW,   cudaEventDisableTiming);
    }
};
static StreamInit s_stream_init;
}

// ---------------- helpers ------------------------------------------------------
DEVINLINE void ldsm4(uint32_t& r0, uint32_t& r1, uint32_t& r2, uint32_t& r3,
                     const f16* p) {
    uint32_t addr = (uint32_t)__cvta_generic_to_shared(p);
    asm volatile("ldmatrix.sync.aligned.m8n8.x4.shared.b16 {%0,%1,%2,%3}, [%4];"
                 : "=r"(r0), "=r"(r1), "=r"(r2), "=r"(r3) : "r"(addr));
}

DEVINLINE void mma_f16(uint32_t c[2], const uint32_t a[4], const uint32_t b[2]) {
    asm volatile("mma.sync.aligned.m16n8k16.row.col.f16.f16.f16.f16 "
                 "{%0,%1},{%2,%3,%4,%5},{%6,%7},{%0,%1};"
                 : "+r"(c[0]), "+r"(c[1])
                 : "r"(a[0]), "r"(a[1]), "r"(a[2]), "r"(a[3]),
                   "r"(b[0]), "r"(b[1]));
}

DEVINLINE void cp16(f16* dst, const f16* src) {
    uint32_t d = (uint32_t)__cvta_generic_to_shared(dst);
    asm volatile("cp.async.cg.shared.global [%0], [%1], 16;" :: "r"(d), "l"(src));
}
DEVINLINE void cp_commit() { asm volatile("cp.async.commit_group;"); }
template<int N> DEVINLINE void cp_wait() {
    asm volatile("cp.async.wait_group %0;" :: "n"(N));
}

DEVINLINE float hsum2(uint32_t h) {
    float2 f = __half22float2(*reinterpret_cast<const __half2*>(&h));
    return f.x + f.y;
}

// ---------------- prep kernels ---------------------------------------------------
// z=0: WkT<-Wk  z=1: WqT<-Wq  z=2: Wo_s copy(x4096)  z=3: WvT<-Wv
__global__ void convert_w_kernel(const float* __restrict__ wq, const float* __restrict__ wk,
                                 const float* __restrict__ wv, const float* __restrict__ wo,
                                 f16* __restrict__ W) {
    __shared__ float t[32][33];
    const int z = blockIdx.z;
    const float* src = (z == 0) ? wk : (z == 1) ? wq : (z == 2) ? wo : wv;
    f16* dst = W + (size_t)z * CH * CH;
    const int r0 = blockIdx.y * 32, c0 = blockIdx.x * 32;
    const int tx = threadIdx.x, ty = threadIdx.y;
    if (z == 2) {
        dst[(size_t)(r0 + ty) * CH + c0 + tx] =
            __float2half(src[(size_t)(r0 + ty) * CH + c0 + tx] * WO_SCALE);
    } else {
        t[ty][tx] = src[(size_t)(r0 + ty) * CH + c0 + tx];
        __syncthreads();
        dst[(size_t)(c0 + ty) * CH + r0 + tx] = __float2half(t[tx][ty]);
    }
}

// x [B][C][HW] fp32 -> XT [B*HW][C] f16.  64x64 tiles, float4 loads,
// pad-65 smem (conflict-free column reads), uint4 f16 stores.
__global__ void __launch_bounds__(256)
xt_kernel(const float* __restrict__ x, f16* __restrict__ XT) {
    __shared__ float tile[64][65];
    const int b  = blockIdx.z;
    const int s0 = blockIdx.x * 64;
    const int c0 = blockIdx.y * 64;
    const int t  = threadIdx.x;
    const int r  = t >> 4;             // 0..15
    const int q4 = (t & 15) * 4;       // float col (0,4,...,60)
    #pragma unroll
    for (int i = 0; i < 4; ++i) {
        const int row = r + i * 16;
        const float4 v = *(const float4*)(x + ((size_t)b * CH + c0 + row) * HWDIM + s0 + q4);
        tile[row][q4]     = v.x;
        tile[row][q4 + 1] = v.y;
        tile[row][q4 + 2] = v.z;
        tile[row][q4 + 3] = v.w;
    }
    __syncthreads();
    #pragma unroll
    for (int i = 0; i < 2; ++i) {
        const int q  = t + i * 256;
        const int j  = q >> 3;          // token within tile (0..63)
        const int cc = (q & 7) * 8;     // channel chunk
        f16 buf[8];
        #pragma unroll
        for (int e = 0; e < 8; ++e)
            buf[e] = __float2half(tile[cc + e][j]);
        *(uint4*)(XT + ((size_t)b * HWDIM + s0 + j) * CH + c0 + cc) = *(uint4*)buf;
    }
}

// a2 = Wk^T bq, wobv = WO_SCALE * (Wo bv)
__global__ void biasvec_kernel(const float* __restrict__ wk, const float* __restrict__ wo,
                               const float* __restrict__ bq, const float* __restrict__ bv,
                               float* __restrict__ a2, float* __restrict__ wobv) {
    const int i = blockIdx.x;
    const int t = threadIdx.x;          // 128 threads
    float s2 = 0.f, s3 = 0.f;
    for (int o = t; o < CH; o += 128) {
        s2 += wk[(size_t)o * CH + i] * bq[o];
        s3 += wo[(size_t)i * CH + o] * bv[o];
    }
    __shared__ float sh[2][128];
    sh[0][t] = s2; sh[1][t] = s3;
    __syncthreads();
    for (int o = 64; o > 0; o >>= 1) {
        if (t < o) {
            sh[0][t] += sh[0][t + o]; sh[1][t] += sh[1][t + o];
        }
        __syncthreads();
    }
    if (t == 0) {
        a2[i]   = sh[0][0];
        wobv[i] = sh[1][0] * WO_SCALE;
    }
}

// sw[t] = SCALE_S * (XT[t] . a2)
__global__ void uw_kernel(const f16* __restrict__ XT,
                          const float* __restrict__ a2,
                          float* __restrict__ sw) {
    const int tok  = blockIdx.x * 8 + (threadIdx.x >> 5);
    const int lane = threadIdx.x & 31;
    const __half2* xr = (const __half2*)(XT + (size_t)tok * CH);
    const float2* p2 = (const float2*)a2;
    float s2 = 0.f;
    #pragma unroll
    for (int j = lane; j < 256; j += 32) {
        float2 xv = __half22float2(xr[j]);
        float2 v2 = p2[j];
        s2 += xv.x * v2.x + xv.y * v2.y;
    }
    #pragma unroll
    for (int o = 16; o > 0; o >>= 1)
        s2 += __shfl_xor_sync(0xffffffffu, s2, o);
    if (lane == 0) sw[tok] = SCALE_S * s2;
}

// ---------------- mini GEMM for the 512x512x512 weight products ------------------
__global__ void __launch_bounds__(128)
mgemm_kernel(const f16* __restrict__ A, const f16* __restrict__ B, f16* __restrict__ C,
             size_t sA_batch, size_t sB_batch, size_t sC_batch)
{
    constexpr int BM = 64, BN = 64, BK = 64;
    constexpr int STAGES = 3;
    constexpr int LDS = BK + 8;         // 72
    constexpr int ASZ = BM * LDS;
    constexpr int BSZ = BN * LDS;
    extern __shared__ f16 smem[];
    f16* sA = smem;
    f16* sB = smem + STAGES * ASZ;

    const int tid  = threadIdx.x;
    const int lane = tid & 31;
    const int warp = tid >> 5;
    const int wm   = warp >> 1;         // 0..1 (32 rows)
    const int wn   = warp & 1;          // 0..1 (32 cols)
    const int bn0  = blockIdx.x * BN;
    const int bm0  = blockIdx.y * BM;
    const int z    = blockIdx.z;

    const f16* Ab = A + (size_t)z * sA_batch;
    const f16* Bb = B + (size_t)z * sB_batch;

    auto load_stage = [&](int stg, int kt) {
        const int ko = kt * BK;
        #pragma unroll
        for (int i = 0; i < 4; ++i) {
            const int q   = tid + i * 128;
            const int row = q >> 3;
            const int col = (q & 7) * 8;
            cp16(sA + stg * ASZ + row * LDS + col, Ab + (size_t)(bm0 + row) * CH + ko + col);
        }
        #pragma unroll
        for (int i = 0; i < 4; ++i) {
            const int q   = tid + i * 128;
            const int row = q >> 3;
            const int col = (q & 7) * 8;
            cp16(sB + stg * BSZ + row * LDS + col, Bb + (size_t)(bn0 + row) * CH + ko + col);
        }
        cp_commit();
    };

    const int nk = CH / BK;   // 8
    load_stage(0, 0);
    load_stage(1, 1);

    uint32_t acc[2][4][2];
    #pragma unroll
    for (int i = 0; i < 2; ++i)
        #pragma unroll
        for (int j = 0; j < 4; ++j) { acc[i][j][0] = 0u; acc[i][j][1] = 0u; }

    const int a_base = (wm * 32 + (lane & 15)) * LDS + (lane >> 4) * 8;
    const int b_base = (wn * 32 + (lane & 7) + ((lane >> 4) & 1) * 8) * LDS
                     + ((lane >> 3) & 1) * 8;

    int s_cur = 0, s_nxt2 = 2;
    for (int kt = 0; kt < nk; ++kt) {
        if (kt + 2 <= nk) cp_wait<1>(); else cp_wait<0>();
        __syncthreads();
        if (kt + 2 < nk) load_stage(s_nxt2, kt + 2);

        const f16* ca = sA + s_cur * ASZ;
        const f16* cb = sB + s_cur * BSZ;
        #pragma unroll
        for (int ks = 0; ks < 4; ++ks) {       // 4 k16 steps in BK=64
            uint32_t af[2][4];
            #pragma unroll
            for (int mf = 0; mf < 2; ++mf)
                ldsm4(af[mf][0], af[mf][1], af[mf][2], af[mf][3],
                      &ca[a_base + mf * 16 * LDS + ks * 16]);
            uint32_t bg[4][2];
            #pragma unroll
            for (int pr = 0; pr < 2; ++pr)
                ldsm4(bg[2 * pr][0], bg[2 * pr][1], bg[2 * pr + 1][0], bg[2 * pr + 1][1],
                      &cb[b_base + pr * 16 * LDS + ks * 16]);
            #pragma unroll
            for (int mf = 0; mf < 2; ++mf)
                #pragma unroll
                for (int nf = 0; nf < 4; ++nf)
                    mma_f16(acc[mf][nf], af[mf], bg[nf]);
        }
        s_cur  = (s_cur == STAGES - 1)  ? 0 : s_cur + 1;
        s_nxt2 = (s_nxt2 == STAGES - 1) ? 0 : s_nxt2 + 1;
    }

    f16* Cb = C + (size_t)z * sC_batch;
    const int r_base = bm0 + wm * 32 + (lane >> 2);
    const int c_base = bn0 + wn * 32 + ((lane & 3) << 1);
    #pragma unroll
    for (int mf = 0; mf < 2; ++mf) {
        #pragma unroll
        for (int nf = 0; nf < 4; ++nf) {
            const int r = r_base + mf * 16;
            const int c = c_base + nf * 8;
            *(__half2*)(Cb + (size_t)r * CH + c)       = *(const __half2*)&acc[mf][nf][0];
            *(__half2*)(Cb + (size_t)(r + 8) * CH + c) = *(const __half2*)&acc[mf][nf][1];
        }
    }
}

// ---------------- GEMM: C[m,n] = sum_k A[m,k]*B[n,k], f16 accum -----------------
// CTA tile 128x256 (BK=32); 8 warps of 64x64. 3-stage cp.async pipeline.
// EPI 1: f16 out, optional row bias (bias1 fp32, nullable)
// EPI 2: f16 out = exp(acc*scale + bias2[z*1024+c])
// EPI 5: fp32 out at [z][r][c]: acc * (1/colsum(B)) * WO_UNSCALE + bias1[r] + aux residual
template<int EPI>
__global__ void __launch_bounds__(256, 2)
gemm_kernel(const f16* __restrict__ A, const f16* __restrict__ B,
            void* __restrict__ Cout,
            int K, int lda, int ldb, int ldc,
            size_t sA_batch, size_t sB_batch, size_t sC_batch,
            const float* __restrict__ bias1, const float* __restrict__ bias2,
            const float* __restrict__ aux, float scale)
{
    constexpr int BM = 128, BN = 256, BK = 32;
    constexpr int STAGES = 3;
    constexpr int LDS = BK + 8;
    constexpr int ASZ = BM * LDS;
    constexpr int BSZ = BN * LDS;
    extern __shared__ f16 smem[];
    f16* sA = smem;
    f16* sB = smem + STAGES * ASZ;

    __shared__ float cs_sh[BN];   // column sums (EPI 5)

    const int tid  = threadIdx.x;
    const int lane = tid & 31;
    const int warp = tid >> 5;
    const int wm   = warp >> 2;
    const int wn   = warp & 3;
    const int bm0  = blockIdx.y * BM;
    const int bn0  = blockIdx.x * BN;
    const int z    = blockIdx.z;

    const f16* Ab = A + (size_t)z * sA_batch;
    const f16* Bb = B + (size_t)z * sB_batch;

    const int arow = tid >> 1;
    const int acol = (tid & 1) * 16;
    const int brow = tid >> 2;
    const int bcol = (tid & 3) * 8;

    const f16* gA = Ab + (size_t)(bm0 + arow) * lda + acol;
    const f16* gB = Bb + (size_t)(bn0 + brow) * ldb + bcol;
    f16* swA = sA + arow * LDS + acol;
    f16* swB = sB + brow * LDS + bcol;

    const int nk = K / BK;

    auto load_stage = [&](int stg, int kt) {
        const int ko = kt * BK;
        f16* dA = swA + stg * ASZ;
        f16* dB = swB + stg * BSZ;
        cp16(dA,     gA + ko);
        cp16(dA + 8, gA + ko + 8);
        #pragma unroll
        for (int i = 0; i < 4; ++i)
            cp16(dB + i * 64 * LDS, gB + (size_t)i * 64 * ldb + ko);
        cp_commit();
    };

    load_stage(0, 0);
    load_stage(1, 1);          // nk >= 16 always here

    uint32_t acc[4][8][2];
    #pragma unroll
    for (int i = 0; i < 4; ++i)
        #pragma unroll
        for (int j = 0; j < 8; ++j) { acc[i][j][0] = 0u; acc[i][j][1] = 0u; }

    float bsum[8];
    if (EPI == 5) {
        #pragma unroll
        for (int i = 0; i < 8; ++i) bsum[i] = 0.f;
    }

    const int a_base = (wm * 64 + (lane & 15)) * LDS + (lane >> 4) * 8;
    const int b_base = (wn * 64 + (lane & 7) + ((lane >> 4) & 1) * 8) * LDS
                     + ((lane >> 3) & 1) * 8;

    int s_cur = 0, s_nxt2 = 2;

    for (int kt = 0; kt < nk; ++kt) {
        if (kt + 2 <= nk) cp_wait<1>(); else cp_wait<0>();
        __syncthreads();

        if (kt + 2 < nk) load_stage(s_nxt2, kt + 2);

        const f16* ca = sA + s_cur * ASZ;
        const f16* cb = sB + s_cur * BSZ;
        #pragma unroll
        for (int ks = 0; ks < 2; ++ks) {
            uint32_t af[4][4];
            #pragma unroll
            for (int mf = 0; mf < 4; ++mf)
                ldsm4(af[mf][0], af[mf][1], af[mf][2], af[mf][3],
                      &ca[a_base + mf * 16 * LDS + ks * 16]);
            uint32_t bg[8][2];
            #pragma unroll
            for (int pr = 0; pr < 4; ++pr)
                ldsm4(bg[2 * pr][0], bg[2 * pr][1], bg[2 * pr + 1][0], bg[2 * pr + 1][1],
                      &cb[b_base + pr * 16 * LDS + ks * 16]);

            if (EPI == 5 && wm == 0) {
                // per-lane partial column sums of B (rows of B = C columns)
                #pragma unroll
                for (int nf = 0; nf < 8; ++nf)
                    bsum[nf] += hsum2(bg[nf][0]) + hsum2(bg[nf][1]);
            }

            #pragma unroll
            for (int mf = 0; mf < 4; ++mf)
                #pragma unroll
                for (int nf = 0; nf < 8; ++nf)
                    mma_f16(acc[mf][nf], af[mf], bg[nf]);
        }

        s_cur  = (s_cur == STAGES - 1)  ? 0 : s_cur + 1;
        s_nxt2 = (s_nxt2 == STAGES - 1) ? 0 : s_nxt2 + 1;
    }

    if (EPI == 5) {
        if (wm == 0) {
            #pragma unroll
            for (int nf = 0; nf < 8; ++nf) {
                float v = bsum[nf];
                v += __shfl_xor_sync(0xffffffffu, v, 1);
                v += __shfl_xor_sync(0xffffffffu, v, 2);
                if ((lane & 3) == 0)
                    cs_sh[wn * 64 + (nf >> 1) * 16 + (nf & 1) * 8 + (lane >> 2)] = v;
            }
        }
        __syncthreads();
    }

    const int r_base = bm0 + wm * 64 + (lane >> 2);
    const int c_base = bn0 + wn * 64 + ((lane & 3) << 1);

    #pragma unroll
    for (int mf = 0; mf < 4; ++mf) {
        #pragma unroll
        for (int nf = 0; nf < 8; ++nf) {
            const int r = r_base + mf * 16;
            const int c = c_base + nf * 8;
            float2 f0 = __half22float2(*(const __half2*)&acc[mf][nf][0]); // (r, c/c+1)
            float2 f1 = __half22float2(*(const __half2*)&acc[mf][nf][1]); // (r+8, c/c+1)

            if (EPI == 1) {
                f16* outp = (f16*)Cout + (size_t)z * sC_batch;
                const float rb0 = bias1 ? bias1[r] : 0.f;
                const float rb1 = bias1 ? bias1[r + 8] : 0.f;
                *(__half2*)(outp + (size_t)r * ldc + c) =
                    __floats2half2_rn(f0.x + rb0, f0.y + rb0);
                *(__half2*)(outp + (size_t)(r + 8) * ldc + c) =
                    __floats2half2_rn(f1.x + rb1, f1.y + rb1);
            } else if (EPI == 2) {
                f16* outp = (f16*)Cout + (size_t)z * sC_batch;
                const float sw0 = bias2[z * HWDIM + c];
                const float sw1 = bias2[z * HWDIM + c + 1];
                *(__half2*)(outp + (size_t)r * ldc + c) =
                    __floats2half2_rn(__expf(f0.x * scale + sw0),
                                      __expf(f0.y * scale + sw1));
                *(__half2*)(outp + (size_t)(r + 8) * ldc + c) =
                    __floats2half2_rn(__expf(f1.x * scale + sw0),
                                      __expf(f1.y * scale + sw1));
            } else {   // EPI == 5 : final fp32 out + residual, column-normalized
                float* outp = (float*)Cout;
                const float inv0 = WO_UNSCALE / cs_sh[c - bn0];
                const float inv1 = WO_UNSCALE / cs_sh[c + 1 - bn0];
                const size_t i0 = (size_t)z * (CH * HWDIM) + (size_t)r * HWDIM + c;
                const size_t i1 = i0 + 8 * HWDIM;
                const float br0 = bias1 ? bias1[r] : 0.f;
                const float br1 = bias1 ? bias1[r + 8] : 0.f;
                const float2 x0 = *(const float2*)(aux + i0);
                const float2 x1 = *(const float2*)(aux + i1);
                *(float2*)(outp + i0) = make_float2(f0.x * inv0 + br0 + x0.x,
                                                    f0.y * inv1 + br0 + x0.y);
                *(float2*)(outp + i1) = make_float2(f1.x * inv0 + br1 + x1.x,
                                                    f1.y * inv1 + br1 + x1.y);
            }
        }
    }
}

// ---------------- launch -----------------------------------------------------------
static constexpr int GEMM_SMEM  = 3 * (128 * 40 + 256 * 40) * (int)sizeof(f16); // 92160
static constexpr int MGEMM_SMEM = 3 * (64 * 72 + 64 * 72) * (int)sizeof(f16);   // 55296

extern "C" void kernel_launch(void* const* d_in, const int* in_sizes, int n_in,
                              void* d_out, int out_size)
{
    (void)in_sizes; (void)n_in; (void)out_size;
    const float* x  = (const float*)d_in[0];
    const float* Wq = (const float*)d_in[1];
    const float* bq = (const float*)d_in[2];
    const float* Wk = (const float*)d_in[3];
    const float* bk = (const float*)d_in[4];
    const float* Wv = (const float*)d_in[5];
    const float* bv = (const float*)d_in[6];
    const float* Wo = (const float*)d_in[7];
    const float* bo = (const float*)d_in[8];
    (void)bk;
    float* out = (float*)d_out;

    f16 *pW, *pM, *pXT, *pT, *pU, *pP;
    float *pA2, *pWOBV, *pSW;
    cudaGetSymbolAddress((void**)&pW,   g_W);
    cudaGetSymbolAddress((void**)&pM,   g_M);
    cudaGetSymbolAddress((void**)&pXT,  g_XT);
    cudaGetSymbolAddress((void**)&pT,   g_T);
    cudaGetSymbolAddress((void**)&pU,   g_U);
    cudaGetSymbolAddress((void**)&pP,   g_P);
    cudaGetSymbolAddress((void**)&pA2,  g_A2);
    cudaGetSymbolAddress((void**)&pWOBV,g_WOBV);
    cudaGetSymbolAddress((void**)&pSW,  g_SW);

    cudaFuncSetAttribute(gemm_kernel<1>, cudaFuncAttributeMaxDynamicSharedMemorySize, GEMM_SMEM);
    cudaFuncSetAttribute(gemm_kernel<2>, cudaFuncAttributeMaxDynamicSharedMemorySize, GEMM_SMEM);
    cudaFuncSetAttribute(gemm_kernel<5>, cudaFuncAttributeMaxDynamicSharedMemorySize, GEMM_SMEM);
    cudaFuncSetAttribute(mgemm_kernel,   cudaFuncAttributeMaxDynamicSharedMemorySize, MGEMM_SMEM);

    // ---- fork side stream for the weight-prep chain --------------------------
    cudaEventRecord(g_evRoot, 0);
    cudaStreamWaitEvent(g_s2, g_evRoot, 0);

    // side stream: convert_w -> biasvec -> mgemm -> evM ; then (after XT) uw -> evSW
    convert_w_kernel<<<dim3(16, 16, 4), dim3(32, 32), 0, g_s2>>>(Wq, Wk, Wv, Wo, pW);
    biasvec_kernel<<<CH, 128, 0, g_s2>>>(Wk, Wo, bq, bv, pA2, pWOBV);
    mgemm_kernel<<<dim3(8, 8, 2), 128, MGEMM_SMEM, g_s2>>>(
        pW, pW + CH * CH, pM,
        (size_t)2 * CH * CH, (size_t)2 * CH * CH, (size_t)CH * CH);
    cudaEventRecord(g_evM, g_s2);

    // main stream: xt -> evXT
    xt_kernel<<<dim3(HWDIM / 64, CH / 64, BATCH), 256>>>(x, pXT);
    cudaEventRecord(g_evXT, 0);

    // side stream: uw (needs XT + a2)
    cudaStreamWaitEvent(g_s2, g_evXT, 0);
    uw_kernel<<<NALL / 8, 256, 0, g_s2>>>(pXT, pA2, pSW);
    cudaEventRecord(g_evSW, g_s2);

    // main stream: big GEMMs (T needs M)
    cudaStreamWaitEvent(0, g_evM, 0);

    // T = X * Ms : M=32768, N=512, K=512  (B = MsT)
    gemm_kernel<1><<<dim3(2, NALL / 128, 1), 256, GEMM_SMEM>>>(
        pXT, pM, pT, CH, CH, CH, CH, 0, 0, 0,
        nullptr, nullptr, nullptr, 1.f);

    // U = Mo * X^T (+wobv rows) : M=512, N=32768, K=512 -> [r][token]
    gemm_kernel<1><<<dim3(NALL / 256, 4, 1), 256, GEMM_SMEM>>>(
        pM + CH * CH, pXT, pU, CH, CH, CH, NALL, 0, 0, 0,
        pWOBV, nullptr, nullptr, 1.f);

    // P needs SW
    cudaStreamWaitEvent(0, g_evSW, 0);

    // P_b = exp(scale*T_b X_b^T + sw_j) : per batch M=N=1024, K=512
    gemm_kernel<2><<<dim3(4, 8, BATCH), 256, GEMM_SMEM>>>(
        pT, pXT, pP, CH, CH, CH, HWDIM,
        (size_t)HWDIM * CH, (size_t)HWDIM * CH, (size_t)HWDIM * HWDIM,
        nullptr, pSW, nullptr, SCALE_S);

    // O_b = U_b P_b^T / colsum + bo + x : M=512, N=1024, K=1024 per batch
    gemm_kernel<5><<<dim3(4, 4, BATCH), 256, GEMM_SMEM>>>(
        pU, pP, out, HWDIM, NALL, HWDIM, HWDIM,
        (size_t)HWDIM, (size_t)HWDIM * HWDIM, 0,
        bo, nullptr, x, 1.f);
}